// round 16
// baseline (speedup 1.0000x reference)
#include <cuda_runtime.h>
#include <cstdint>

#define BATCH 256
#define DIM   2048
#define PNUM  56
#define CH    16                       // 128-col chunks per batch row
#define GRID1 (BATCH * CH)             // 4096

// smem layout (floats)
#define S_P    0                       // 56 x 132 (128 cols + 4 pad)
#define RPAD   132
#define S_M    (56 * RPAD)             // 7392: mean, 128 floats
#define S_MG   (S_M + 128)             // m - g, 128 floats
#define S_RED  (S_MG + 128)            // 8 x 128 mean partials / dcl fold (1024)
#define SMEMF  (S_RED + 1024)          // 8672 floats = 34688 bytes

#define KEXP  0.3606737602222409f

typedef unsigned long long u64;

// --- device scratch (zero-init; finalizer self-resets for graph replay) ---
__device__ unsigned int g_done;
__device__ float4 g_row[BATCH * PNUM];       // per (b,p): se_x, se_y, su_x, su_y
__device__ float4 g_dilB[BATCH];             // per b: se_g, se_m, su_g, su_m

__device__ __forceinline__ float ex2f(float x) {
    float r; asm("ex2.approx.ftz.f32 %0, %1;" : "=f"(r) : "f"(x)); return r;
}
__device__ __forceinline__ u64 f2_add(u64 a, u64 b) {
    u64 r; asm("add.rn.f32x2 %0, %1, %2;" : "=l"(r) : "l"(a), "l"(b)); return r;
}
__device__ __forceinline__ u64 f2_mul(u64 a, u64 b) {
    u64 r; asm("mul.rn.f32x2 %0, %1, %2;" : "=l"(r) : "l"(a), "l"(b)); return r;
}
__device__ __forceinline__ u64 f2_fma(u64 a, u64 b, u64 c) {
    u64 r; asm("fma.rn.f32x2 %0, %1, %2, %3;" : "=l"(r) : "l"(a), "l"(b), "l"(c)); return r;
}
__device__ __forceinline__ void f2_unpack(u64 v, float& lo, float& hi) {
    asm("mov.b64 {%0, %1}, %2;" : "=f"(lo), "=f"(hi) : "l"(v));
}
__device__ __forceinline__ u64 f2_pack(float lo, float hi) {
    u64 r; asm("mov.b64 %0, {%1, %2};" : "=l"(r) : "f"(lo), "f"(hi)); return r;
}
__device__ __forceinline__ float4 ld_cv4(const float4* p) {
    float4 v;
    asm volatile("ld.global.cv.v4.f32 {%0,%1,%2,%3}, [%4];"
                 : "=f"(v.x), "=f"(v.y), "=f"(v.z), "=f"(v.w) : "l"(p));
    return v;
}

#define F2_NEG1 0xBF800000BF800000ULL
#define F2_KK   0x3EB8AA3B3EB8AA3BULL   /* (KEXP, KEXP) */
#define F2_I56  0x3C9249253C924925ULL   /* (1/56, 1/56) */

// ============================================================================
// k1: block = (b, 128-col chunk), 256 threads, 5 blocks/SM.
// A: load 56 rows -> smem + mean partials. Mid: fold mean, mg, dil -> REDG.
// C: dcl partials -> fold -> REDG per (b,p) row.
// Tail: single release fence by tid0 per block; last arriving block acquires,
// reads 229KB of accumulators, finalizes both losses, writes out, resets.
// ============================================================================
__global__ void __launch_bounds__(256, 5) k1(const float* __restrict__ ebp,
                                             const float* __restrict__ ebg,
                                             float* __restrict__ out) {
    extern __shared__ float sm[];
    __shared__ int s_last;
    __shared__ double sacc[16];
    int bo = blockIdx.x;
    int b  = bo >> 4;
    int ch = bo & 15;
    int tid = threadIdx.x;

    // ---- Phase A: load 56 x 32 float4 + mean partials ----
    int rg = tid >> 5;          // 0..7, rows rg, rg+8, ..., rg+48
    int c4 = tid & 31;          // float4 index in chunk
    const ulonglong2* eb = (const ulonglong2*)ebp;
    size_t coff = (size_t)ch * 32 + c4;
    u64 aLo = 0, aHi = 0;
#pragma unroll 7
    for (int i = 0; i < 7; i++) {
        int p = i * 8 + rg;
        ulonglong2 v = eb[(size_t)(p * BATCH + b) * 512 + coff];
        *(ulonglong2*)&sm[S_P + p * RPAD + c4 * 4] = v;
        aLo = f2_add(aLo, v.x);
        aHi = f2_add(aHi, v.y);
    }
    *(ulonglong2*)&sm[S_RED + rg * 128 + c4 * 4] = make_ulonglong2(aLo, aHi);
    __syncthreads();

    // ---- Mid: fold mean, mg, dil partial (threads 0..31) ----
    if (tid < 32) {
        u64 mLo = 0, mHi = 0;
#pragma unroll 8
        for (int k = 0; k < 8; k++) {
            ulonglong2 v = *(ulonglong2*)&sm[S_RED + k * 128 + tid * 4];
            mLo = f2_add(mLo, v.x); mHi = f2_add(mHi, v.y);
        }
        mLo = f2_mul(mLo, F2_I56); mHi = f2_mul(mHi, F2_I56);
        ulonglong2 g = ((const ulonglong2*)ebg)[(size_t)b * 512 + coff];
        u64 mgLo = f2_fma(g.x, F2_NEG1, mLo);
        u64 mgHi = f2_fma(g.y, F2_NEG1, mHi);
        *(ulonglong2*)&sm[S_M  + tid * 4] = make_ulonglong2(mLo, mHi);
        *(ulonglong2*)&sm[S_MG + tid * 4] = make_ulonglong2(mgLo, mgHi);

        float m0, m1, m2, m3, g0, g1, g2, g3, u0, u1, u2, u3;
        f2_unpack(mLo, m0, m1); f2_unpack(mHi, m2, m3);
        f2_unpack(g.x, g0, g1); f2_unpack(g.y, g2, g3);
        f2_unpack(mgLo, u0, u1); f2_unpack(mgHi, u2, u3);
        float se_g = 0.f, se_m = 0.f, su_g = 0.f, su_m = 0.f;
#define DIL1(gg, mm, uu) { float eg = ex2f(gg * KEXP);          \
                           float em = ex2f(mm * KEXP);          \
                           se_g += eg; se_m += em;              \
                           su_g = fmaf(eg, uu, su_g);           \
                           su_m = fmaf(em, uu, su_m); }
        DIL1(g0, m0, u0) DIL1(g1, m1, u1) DIL1(g2, m2, u2) DIL1(g3, m3, u3)
#undef DIL1
#pragma unroll
        for (int off = 16; off; off >>= 1) {
            se_g += __shfl_xor_sync(0xffffffffu, se_g, off);
            se_m += __shfl_xor_sync(0xffffffffu, se_m, off);
            su_g += __shfl_xor_sync(0xffffffffu, su_g, off);
            su_m += __shfl_xor_sync(0xffffffffu, su_m, off);
        }
        if (tid == 0) {
            float* d = (float*)&g_dilB[b];
            atomicAdd(d + 0, se_g); atomicAdd(d + 1, se_m);
            atomicAdd(d + 2, su_g); atomicAdd(d + 3, su_m);
        }
    }
    __syncthreads();

    // ---- Phase C: per-thread dcl partials (tid < 224) ----
    int s = tid / 56;                  // subchunk 0..3
    int r = tid - s * 56;              // row 0..55
    if (s < 4) {
        int j0 = s * 8;
        u64 seX = 0, seY = 0, suX = 0, suY = 0;
#pragma unroll 8
        for (int j = 0; j < 8; j++) {
            ulonglong2 P  = *(ulonglong2*)&sm[S_P  + r * RPAD + (j0 + j) * 4];
            ulonglong2 M  = *(ulonglong2*)&sm[S_M  + (j0 + j) * 4];
            ulonglong2 MG = *(ulonglong2*)&sm[S_MG + (j0 + j) * 4];
#define DCLP(pp, mm, gm) {                                       \
            u64 db = f2_fma(pp, F2_NEG1, mm);    /* m - p */     \
            u64 dg = f2_fma(gm, F2_NEG1, db);    /* g - p */     \
            u64 w  = f2_add(db, dg);                             \
            u64 u  = f2_mul(gm, w);                              \
            u64 ax = f2_mul(f2_mul(dg, dg), F2_KK);              \
            u64 ay = f2_mul(f2_mul(db, db), F2_KK);              \
            float a0, a1, b0, b1;                                \
            f2_unpack(ax, a0, a1); f2_unpack(ay, b0, b1);        \
            u64 ex = f2_pack(ex2f(a0), ex2f(a1));                \
            u64 ey = f2_pack(ex2f(b0), ex2f(b1));                \
            seX = f2_add(seX, ex); seY = f2_add(seY, ey);        \
            suX = f2_fma(ex, u, suX); suY = f2_fma(ey, u, suY); }
            DCLP(P.x, M.x, MG.x)
            DCLP(P.y, M.y, MG.y)
#undef DCLP
        }
        float x0, x1, y0, y1, z0, z1, w0, w1;
        f2_unpack(seX, x0, x1); f2_unpack(seY, y0, y1);
        f2_unpack(suX, z0, z1); f2_unpack(suY, w0, w1);
        *(float4*)&sm[S_RED + (s * 56 + r) * 4] =
            make_float4(x0 + x1, y0 + y1, z0 + z1, w0 + w1);
    }
    __syncthreads();

    // ---- fold 4 subchunks -> REDG per (b,p) row ----
    if (tid < 56) {
        float4 a = *(float4*)&sm[S_RED + (0 * 56 + tid) * 4];
        float4 c = *(float4*)&sm[S_RED + (1 * 56 + tid) * 4];
        float4 d = *(float4*)&sm[S_RED + (2 * 56 + tid) * 4];
        float4 e = *(float4*)&sm[S_RED + (3 * 56 + tid) * 4];
        float* dst = (float*)&g_row[b * PNUM + tid];
        atomicAdd(dst + 0, a.x + c.x + d.x + e.x);
        atomicAdd(dst + 1, a.y + c.y + d.y + e.y);
        atomicAdd(dst + 2, a.z + c.z + d.z + e.z);
        atomicAdd(dst + 3, a.w + c.w + d.w + e.w);
    }

    // ---- Tail: single release-fence per block, last block finalizes ----
    __syncthreads();                    // block's REDGs happen-before tid0 below
    if (tid == 0) {
        __threadfence();                // cumulative release (ONE thread/block)
        s_last = (atomicAdd(&g_done, 1u) == GRID1 - 1) ? 1 : 0;
    }
    __syncthreads();
    if (!s_last) return;

    __threadfence();                    // acquire side; one block only
    int lane = tid & 31, w = tid >> 5;
    double dcl = 0.0;
#pragma unroll 14
    for (int k = 0; k < PNUM; k++) {
        int row = k * 256 + tid;        // 0..14335
        float4 v = ld_cv4(&g_row[row]);
        g_row[row] = make_float4(0.f, 0.f, 0.f, 0.f);   // self-reset
        dcl += (double)(v.w / v.y - v.z / v.x);
    }
    float4 dv = ld_cv4(&g_dilB[tid]);   // b = tid
    g_dilB[tid] = make_float4(0.f, 0.f, 0.f, 0.f);
    double dil = (double)(dv.w / dv.y - dv.z / dv.x);
#pragma unroll
    for (int off = 16; off; off >>= 1) {
        dcl += __shfl_xor_sync(0xffffffffu, dcl, off);
        dil += __shfl_xor_sync(0xffffffffu, dil, off);
    }
    if (lane == 0) { sacc[w] = dcl; sacc[w + 8] = dil; }
    __syncthreads();
    if (tid == 0) {
        double sd = 0.0, si = 0.0;
#pragma unroll
        for (int i = 0; i < 8; i++) { sd += sacc[i]; si += sacc[i + 8]; }
        out[0] = (float)(si * (4.0 / (double)DIM));
        out[1] = (float)(sd * (4.0 / ((double)DIM * (double)PNUM)));
        g_done = 0u;                    // self-reset for next replay
    }
}

extern "C" void kernel_launch(void* const* d_in, const int* in_sizes, int n_in,
                              void* d_out, int out_size) {
    const float* ebg = (const float*)d_in[0];
    const float* ebp = (const float*)d_in[1];
    (void)in_sizes; (void)n_in; (void)out_size;

    cudaFuncSetAttribute(k1, cudaFuncAttributeMaxDynamicSharedMemorySize,
                         SMEMF * sizeof(float));
    k1<<<GRID1, 256, SMEMF * sizeof(float)>>>(ebp, ebg, (float*)d_out);
}

// round 17
// speedup vs baseline: 1.7165x; 1.7165x over previous
#include <cuda_runtime.h>
#include <cstdint>

#define BATCH 256
#define DIM   2048
#define PNUM  56
#define CH    16                       // 128-col chunks per batch row
#define GRID1 (BATCH * CH)             // 4096
#define GRID2 57                       // 56 dcl blocks + 1 dil block

// smem layout (floats)
#define S_P    0                       // 56 x 132 (128 cols + 4 pad)
#define RPAD   132
#define S_M    (56 * RPAD)             // 7392: mean, 128 floats
#define S_MG   (S_M + 128)             // m - g, 128 floats
#define S_RED  (S_MG + 128)            // 8 x 128 mean partials / dcl fold (1024)
#define SMEMF  (S_RED + 1024)          // 8672 floats = 34688 bytes

#define KEXP  0.3606737602222409f

typedef unsigned long long u64;

// --- device scratch (zero-init; k1 block0 resets accs, k2 resets rows) ---
__device__ double g_acc0;                    // dil
__device__ double g_acc1;                    // dcl
__device__ unsigned int g_done;
__device__ float4 g_row[BATCH * PNUM];       // per (b,p): se_x, se_y, su_x, su_y
__device__ float4 g_dilB[BATCH];             // per b: se_g, se_m, su_g, su_m

__device__ __forceinline__ float ex2f(float x) {
    float r; asm("ex2.approx.ftz.f32 %0, %1;" : "=f"(r) : "f"(x)); return r;
}
__device__ __forceinline__ u64 f2_add(u64 a, u64 b) {
    u64 r; asm("add.rn.f32x2 %0, %1, %2;" : "=l"(r) : "l"(a), "l"(b)); return r;
}
__device__ __forceinline__ u64 f2_mul(u64 a, u64 b) {
    u64 r; asm("mul.rn.f32x2 %0, %1, %2;" : "=l"(r) : "l"(a), "l"(b)); return r;
}
__device__ __forceinline__ u64 f2_fma(u64 a, u64 b, u64 c) {
    u64 r; asm("fma.rn.f32x2 %0, %1, %2, %3;" : "=l"(r) : "l"(a), "l"(b), "l"(c)); return r;
}
__device__ __forceinline__ void f2_unpack(u64 v, float& lo, float& hi) {
    asm("mov.b64 {%0, %1}, %2;" : "=f"(lo), "=f"(hi) : "l"(v));
}
__device__ __forceinline__ u64 f2_pack(float lo, float hi) {
    u64 r; asm("mov.b64 %0, {%1, %2};" : "=l"(r) : "f"(lo), "f"(hi)); return r;
}

#define F2_NEG1 0xBF800000BF800000ULL
#define F2_KK   0x3EB8AA3B3EB8AA3BULL   /* (KEXP, KEXP) */
#define F2_I56  0x3C9249253C924925ULL   /* (1/56, 1/56) */

// ============================================================================
// k1: block = (b, 128-col chunk), 256 threads, 5 blocks/SM.
// A: load 56 rows -> smem + mean partials. Mid: fold mean, mg, dil -> REDG.
// C: dcl partials -> fold -> REDG per (b,p) row. PDL trigger at end.
// ============================================================================
__global__ void __launch_bounds__(256, 5) k1(const float* __restrict__ ebp,
                                             const float* __restrict__ ebg) {
    extern __shared__ float sm[];
    int bo = blockIdx.x;
    int b  = bo >> 4;
    int ch = bo & 15;
    int tid = threadIdx.x;

    if (bo == 0 && tid == 0) { g_acc0 = 0.0; g_acc1 = 0.0; g_done = 0u; }

    // ---- Phase A: load 56 x 32 float4 + mean partials ----
    int rg = tid >> 5;          // 0..7, rows rg, rg+8, ..., rg+48
    int c4 = tid & 31;          // float4 index in chunk
    const ulonglong2* eb = (const ulonglong2*)ebp;
    size_t coff = (size_t)ch * 32 + c4;
    u64 aLo = 0, aHi = 0;
#pragma unroll 7
    for (int i = 0; i < 7; i++) {
        int p = i * 8 + rg;
        ulonglong2 v = eb[(size_t)(p * BATCH + b) * 512 + coff];
        *(ulonglong2*)&sm[S_P + p * RPAD + c4 * 4] = v;
        aLo = f2_add(aLo, v.x);
        aHi = f2_add(aHi, v.y);
    }
    *(ulonglong2*)&sm[S_RED + rg * 128 + c4 * 4] = make_ulonglong2(aLo, aHi);
    __syncthreads();

    // ---- Mid: fold mean, mg, dil partial (threads 0..31) ----
    if (tid < 32) {
        u64 mLo = 0, mHi = 0;
#pragma unroll 8
        for (int k = 0; k < 8; k++) {
            ulonglong2 v = *(ulonglong2*)&sm[S_RED + k * 128 + tid * 4];
            mLo = f2_add(mLo, v.x); mHi = f2_add(mHi, v.y);
        }
        mLo = f2_mul(mLo, F2_I56); mHi = f2_mul(mHi, F2_I56);
        ulonglong2 g = ((const ulonglong2*)ebg)[(size_t)b * 512 + coff];
        u64 mgLo = f2_fma(g.x, F2_NEG1, mLo);
        u64 mgHi = f2_fma(g.y, F2_NEG1, mHi);
        *(ulonglong2*)&sm[S_M  + tid * 4] = make_ulonglong2(mLo, mHi);
        *(ulonglong2*)&sm[S_MG + tid * 4] = make_ulonglong2(mgLo, mgHi);

        float m0, m1, m2, m3, g0, g1, g2, g3, u0, u1, u2, u3;
        f2_unpack(mLo, m0, m1); f2_unpack(mHi, m2, m3);
        f2_unpack(g.x, g0, g1); f2_unpack(g.y, g2, g3);
        f2_unpack(mgLo, u0, u1); f2_unpack(mgHi, u2, u3);
        float se_g = 0.f, se_m = 0.f, su_g = 0.f, su_m = 0.f;
#define DIL1(gg, mm, uu) { float eg = ex2f(gg * KEXP);          \
                           float em = ex2f(mm * KEXP);          \
                           se_g += eg; se_m += em;              \
                           su_g = fmaf(eg, uu, su_g);           \
                           su_m = fmaf(em, uu, su_m); }
        DIL1(g0, m0, u0) DIL1(g1, m1, u1) DIL1(g2, m2, u2) DIL1(g3, m3, u3)
#undef DIL1
#pragma unroll
        for (int off = 16; off; off >>= 1) {
            se_g += __shfl_xor_sync(0xffffffffu, se_g, off);
            se_m += __shfl_xor_sync(0xffffffffu, se_m, off);
            su_g += __shfl_xor_sync(0xffffffffu, su_g, off);
            su_m += __shfl_xor_sync(0xffffffffu, su_m, off);
        }
        if (tid == 0) {
            float* d = (float*)&g_dilB[b];
            atomicAdd(d + 0, se_g); atomicAdd(d + 1, se_m);
            atomicAdd(d + 2, su_g); atomicAdd(d + 3, su_m);
        }
    }
    __syncthreads();

    // ---- Phase C: per-thread dcl partials (tid < 224) ----
    int s = tid / 56;                  // subchunk 0..3
    int r = tid - s * 56;              // row 0..55
    if (s < 4) {
        int j0 = s * 8;
        u64 seX = 0, seY = 0, suX = 0, suY = 0;
#pragma unroll 8
        for (int j = 0; j < 8; j++) {
            ulonglong2 P  = *(ulonglong2*)&sm[S_P  + r * RPAD + (j0 + j) * 4];
            ulonglong2 M  = *(ulonglong2*)&sm[S_M  + (j0 + j) * 4];
            ulonglong2 MG = *(ulonglong2*)&sm[S_MG + (j0 + j) * 4];
#define DCLP(pp, mm, gm) {                                       \
            u64 db = f2_fma(pp, F2_NEG1, mm);    /* m - p */     \
            u64 dg = f2_fma(gm, F2_NEG1, db);    /* g - p */     \
            u64 w  = f2_add(db, dg);                             \
            u64 u  = f2_mul(gm, w);                              \
            u64 ax = f2_mul(f2_mul(dg, dg), F2_KK);              \
            u64 ay = f2_mul(f2_mul(db, db), F2_KK);              \
            float a0, a1, b0, b1;                                \
            f2_unpack(ax, a0, a1); f2_unpack(ay, b0, b1);        \
            u64 ex = f2_pack(ex2f(a0), ex2f(a1));                \
            u64 ey = f2_pack(ex2f(b0), ex2f(b1));                \
            seX = f2_add(seX, ex); seY = f2_add(seY, ey);        \
            suX = f2_fma(ex, u, suX); suY = f2_fma(ey, u, suY); }
            DCLP(P.x, M.x, MG.x)
            DCLP(P.y, M.y, MG.y)
#undef DCLP
        }
        float x0, x1, y0, y1, z0, z1, w0, w1;
        f2_unpack(seX, x0, x1); f2_unpack(seY, y0, y1);
        f2_unpack(suX, z0, z1); f2_unpack(suY, w0, w1);
        *(float4*)&sm[S_RED + (s * 56 + r) * 4] =
            make_float4(x0 + x1, y0 + y1, z0 + z1, w0 + w1);
    }
    __syncthreads();

    // ---- fold 4 subchunks -> REDG per (b,p) row ----
    if (tid < 56) {
        float4 a = *(float4*)&sm[S_RED + (0 * 56 + tid) * 4];
        float4 c = *(float4*)&sm[S_RED + (1 * 56 + tid) * 4];
        float4 d = *(float4*)&sm[S_RED + (2 * 56 + tid) * 4];
        float4 e = *(float4*)&sm[S_RED + (3 * 56 + tid) * 4];
        float* dst = (float*)&g_row[b * PNUM + tid];
        atomicAdd(dst + 0, a.x + c.x + d.x + e.x);
        atomicAdd(dst + 1, a.y + c.y + d.y + e.y);
        atomicAdd(dst + 2, a.z + c.z + d.z + e.z);
        atomicAdd(dst + 3, a.w + c.w + d.w + e.w);
    }

#if __CUDA_ARCH__ >= 900
    cudaTriggerProgrammaticLaunchCompletion();
#endif
}

// ============================================================================
// k2: 57 blocks, PDL-gated. Blocks 0..55: one (b,p) row per thread -> divide
// -> block reduce -> dcl atomic; resets g_row. Block 56: dil per thread b ->
// dil atomic; resets g_dilB. Last finished block writes out.
// ============================================================================
__global__ void __launch_bounds__(256) k2(float* __restrict__ out) {
    __shared__ double sacc[8];
    __shared__ int s_last;
#if __CUDA_ARCH__ >= 900
    cudaGridDependencySynchronize();    // wait for k1 completion + visibility
#endif
    int tid = threadIdx.x, lane = tid & 31, w = tid >> 5;

    double t;
    if (blockIdx.x < 56) {
        int row = blockIdx.x * 256 + tid;       // 0..14335
        float4 v = g_row[row];
        g_row[row] = make_float4(0.f, 0.f, 0.f, 0.f);   // self-reset for replay
        t = (double)(v.w / v.y - v.z / v.x);
    } else {
        float4 v = g_dilB[tid];                 // b = tid
        g_dilB[tid] = make_float4(0.f, 0.f, 0.f, 0.f);
        t = (double)(v.w / v.y - v.z / v.x);
    }
#pragma unroll
    for (int off = 16; off; off >>= 1)
        t += __shfl_xor_sync(0xffffffffu, t, off);
    if (lane == 0) sacc[w] = t;
    __syncthreads();
    if (tid == 0) {
        double s = 0.0;
#pragma unroll
        for (int i = 0; i < 8; i++) s += sacc[i];
        atomicAdd((blockIdx.x < 56) ? &g_acc1 : &g_acc0, s);
    }

    __threadfence();
    __syncthreads();
    if (tid == 0) {
        unsigned prev = atomicAdd(&g_done, 1u);
        s_last = (prev == GRID2 - 1) ? 1 : 0;
    }
    __syncthreads();
    if (s_last && tid == 0) {
        __threadfence();
        double a0 = *(volatile double*)&g_acc0;
        double a1 = *(volatile double*)&g_acc1;
        out[0] = (float)(a0 * (4.0 / (double)DIM));
        out[1] = (float)(a1 * (4.0 / ((double)DIM * (double)PNUM)));
    }
}

extern "C" void kernel_launch(void* const* d_in, const int* in_sizes, int n_in,
                              void* d_out, int out_size) {
    const float* ebg = (const float*)d_in[0];
    const float* ebp = (const float*)d_in[1];
    (void)in_sizes; (void)n_in; (void)out_size;

    cudaFuncSetAttribute(k1, cudaFuncAttributeMaxDynamicSharedMemorySize,
                         SMEMF * sizeof(float));
    k1<<<GRID1, 256, SMEMF * sizeof(float)>>>(ebp, ebg);

    // PDL launch of k2: grid spins up during k1, gated by griddepsync.
    cudaLaunchConfig_t cfg = {};
    cfg.gridDim  = dim3(GRID2);
    cfg.blockDim = dim3(256);
    cfg.dynamicSmemBytes = 0;
    cfg.stream = 0;                     // legacy default stream (same as <<<>>>)
    cudaLaunchAttribute attr[1];
    attr[0].id = cudaLaunchAttributeProgrammaticStreamSerialization;
    attr[0].val.programmaticStreamSerializationAllowed = 1;
    cfg.attrs = attr;
    cfg.numAttrs = 1;
    cudaLaunchKernelEx(&cfg, k2, (float*)d_out);
}